// round 12
// baseline (speedup 1.0000x reference)
#include <cuda_runtime.h>
#include <cstdint>

static constexpr int NL   = 4096;    // coarse points
static constexpr int NH   = 16384;   // fine points
static constexpr int NF   = 256;     // features
static constexpr int PPB  = 56;      // fine points per block
static constexpr int SUBS = 8;       // candidate slices
static constexpr int TPB  = PPB * SUBS;   // 448 threads, 14 warps
static constexpr int GRID = (NH + PPB - 1) / PPB;  // 293 -> 2 blocks/SM on 147 SMs
static constexpr int HALF = 2048;    // candidates staged per chunk (32 KB packed)
static constexpr int NPAIR = HALF / 2;     // 1024 staged pairs
static constexpr int WPAIR = NPAIR / SUBS; // 128 pairs per sub per chunk

// packed f32x2 helpers (sm_103a FFMA2 — PTX-only, ptxas never auto-fuses)
__device__ __forceinline__ uint64_t ffma2(uint64_t a, uint64_t b, uint64_t c) {
    uint64_t d;
    asm("fma.rn.f32x2 %0, %1, %2, %3;" : "=l"(d) : "l"(a), "l"(b), "l"(c));
    return d;
}
__device__ __forceinline__ uint64_t pack2(float lo, float hi) {
    uint64_t r;
    asm("mov.b64 %0, {%1, %2};" : "=l"(r) : "f"(lo), "f"(hi));
    return r;
}
__device__ __forceinline__ void unpack2(float& lo, float& hi, uint64_t v) {
    asm("mov.b64 {%0, %1}, %2;" : "=f"(lo), "=f"(hi) : "l"(v));
}

__global__ __launch_bounds__(TPB, 2)
void knn_interp_kernel(const float* __restrict__ x,
                       const float* __restrict__ pos_l,
                       const float* __restrict__ pos_h,
                       float* __restrict__ out)
{
    // 32 KB buffer: pair-packed candidate table during the scan, then reused
    // (after a barrier) for the per-sub partial top-3 merge arrays (~10.8 KB).
    __shared__ __align__(16) char smemBuf[HALF * 16];
    __shared__ int   sIdx[PPB][3];
    __shared__ float sW[PPB][3];

    // QA[j] = (xpair, ypair), QB[j] = (zpair, wpair); x=-2lx etc., w=|l|^2
    ulonglong2* sQA = reinterpret_cast<ulonglong2*>(smemBuf);            // 16 KB
    ulonglong2* sQB = reinterpret_cast<ulonglong2*>(smemBuf + HALF*8);   // 16 KB
    float (*sMs)[PPB][3] = reinterpret_cast<float (*)[PPB][3]>(smemBuf);
    int   (*sMi)[PPB][3] = reinterpret_cast<int   (*)[PPB][3]>(smemBuf + SUBS*PPB*3*4);

    const int tid  = threadIdx.x;
    const int sub  = tid / PPB;        // 0..7 : candidate slice
    const int p    = tid - sub * PPB;  // 0..55 : fine point within block
    const int hbase = blockIdx.x * PPB;
    const int npts = min(PPB, NH - hbase);        // tail block: 32 valid points
    const int h    = hbase + min(p, npts - 1);    // clamp: invalid lanes discarded later

    const float hx = pos_h[3*h+0];
    const float hy = pos_h[3*h+1];
    const float hz = pos_h[3*h+2];
    const uint64_t hx2 = pack2(hx, hx);
    const uint64_t hy2 = pack2(hy, hy);
    const uint64_t hz2 = pack2(hz, hz);

    // Partial top-3 by score = |l|^2 - 2 h.l (bit-identical to flat-scan R5/R8/R11)
    float s0 = 3.4e38f, s1 = 3.4e38f, s2 = 3.4e38f;
    int   i0 = 0, i1 = 0, i2 = 0;

    auto insert = [&](float s, int g) {   // same nested form as R5/R8/R11 (proven codegen)
        if (s < s1) {
            s2 = s1; i2 = i1;
            if (s < s0) { s1 = s0; i1 = i0; s0 = s; i0 = g; }
            else        { s1 = s;  i1 = g; }
        } else { s2 = s; i2 = g; }
    };

    #pragma unroll 1
    for (int half = 0; half < NL / HALF; ++half) {
        const int base = half * HALF;
        __syncthreads();
        // stage: 1024 pairs by 448 threads
        for (int pj = tid; pj < NPAIR; pj += TPB) {
            const int g  = base + 2*pj;
            const float ax = pos_l[3*g+0], ay = pos_l[3*g+1], az = pos_l[3*g+2];
            const float bx = pos_l[3*g+3], by = pos_l[3*g+4], bz = pos_l[3*g+5];
            const float wa = fmaf(ax, ax, fmaf(ay, ay, az*az));
            const float wb = fmaf(bx, bx, fmaf(by, by, bz*bz));
            sQA[pj] = make_ulonglong2(pack2(-2.0f*ax, -2.0f*bx),
                                      pack2(-2.0f*ay, -2.0f*by));
            sQB[pj] = make_ulonglong2(pack2(-2.0f*az, -2.0f*bz),
                                      pack2(wa, wb));
        }
        __syncthreads();

        const int pb = sub * WPAIR;            // warp-level LDS broadcast/coalesced
        const int gb = base + 2*pb;
        #pragma unroll 8
        for (int jp = 0; jp < WPAIR; ++jp) {
            const ulonglong2 qa = sQA[pb + jp];   // (xpair, ypair)
            const ulonglong2 qb = sQB[pb + jp];   // (zpair, wpair)
            uint64_t t = ffma2(qb.x, hz2, qb.y);
            t = ffma2(qa.y, hy2, t);
            t = ffma2(qa.x, hx2, t);
            float sa, sb;
            unpack2(sa, sb, t);
            const int g = gb + 2*jp;
            if (sa < s2) insert(sa, g);       // sequential order preserved:
            if (sb < s2) insert(sb, g + 1);   // a first, then b
        }
    }

    __syncthreads();   // all reads of sQA/sQB done -> safe to alias as merge buffers
    sMs[sub][p][0] = s0; sMs[sub][p][1] = s1; sMs[sub][p][2] = s2;
    sMi[sub][p][0] = i0; sMi[sub][p][1] = i1; sMi[sub][p][2] = i2;
    __syncthreads();

    // Merge 8 partial top-3s -> final top-3; exact-d2 weights.
    // Threads tid<npts have p==tid, so (hx,hy,hz) already hold this point's coords.
    if (tid < npts) {
        float b0 = 3.4e38f, b1 = 3.4e38f, b2 = 3.4e38f;
        int   j0 = 0, j1 = 0, j2 = 0;
        #pragma unroll
        for (int ss = 0; ss < SUBS; ++ss) {
            #pragma unroll
            for (int k = 0; k < 3; ++k) {
                const float s = sMs[ss][tid][k];
                const int   g = sMi[ss][tid][k];
                if (s < b2) {
                    if (s < b1) {
                        b2 = b1; j2 = j1;
                        if (s < b0) { b1 = b0; j1 = j0; b0 = s; j0 = g; }
                        else        { b1 = s;  j1 = g; }
                    } else { b2 = s; j2 = g; }
                }
            }
        }
        // Exact squared distances for the 3 selected (matches reference recompute)
        const int id[3] = {j0, j1, j2};
        float w[3], wsum = 0.0f;
        #pragma unroll
        for (int k = 0; k < 3; ++k) {
            const float lx = pos_l[3*id[k]+0];
            const float ly = pos_l[3*id[k]+1];
            const float lz = pos_l[3*id[k]+2];
            const float dx = hx - lx, dy = hy - ly, dz = hz - lz;
            const float d2 = fmaf(dx, dx, fmaf(dy, dy, dz*dz));
            const float wk = 1.0f / fmaxf(d2, 1e-16f);
            w[k] = wk;
            wsum += wk;
        }
        const float inv = 1.0f / wsum;
        sIdx[tid][0] = id[0]; sIdx[tid][1] = id[1]; sIdx[tid][2] = id[2];
        sW[tid][0] = w[0]*inv; sW[tid][1] = w[1]*inv; sW[tid][2] = w[2]*inv;
    }
    __syncthreads();

    // Phase B: gather + weighted sum. One warp per fine point, float4-coalesced.
    const int warp = tid >> 5, lane = tid & 31;   // 14 warps
    const float4* __restrict__ x4 = reinterpret_cast<const float4*>(x);
    float4* __restrict__ o4 = reinterpret_cast<float4*>(out);
    const int rowq = NF / 4;   // 64 float4 per feature row

    for (int pp = warp; pp < npts; pp += 14) {
        const int hh = hbase + pp;
        const int a = sIdx[pp][0], b = sIdx[pp][1], c = sIdx[pp][2];
        const float w0 = sW[pp][0], w1 = sW[pp][1], w2 = sW[pp][2];
        const float4* __restrict__ ra = x4 + a * rowq;
        const float4* __restrict__ rb = x4 + b * rowq;
        const float4* __restrict__ rc = x4 + c * rowq;
        float4* __restrict__ ro = o4 + hh * rowq;
        #pragma unroll
        for (int ch = lane; ch < rowq; ch += 32) {
            const float4 va = ra[ch];
            const float4 vb = rb[ch];
            const float4 vc = rc[ch];
            float4 r;
            r.x = fmaf(w2, vc.x, fmaf(w1, vb.x, w0 * va.x));
            r.y = fmaf(w2, vc.y, fmaf(w1, vb.y, w0 * va.y));
            r.z = fmaf(w2, vc.z, fmaf(w1, vb.z, w0 * va.z));
            r.w = fmaf(w2, vc.w, fmaf(w1, vb.w, w0 * va.w));
            ro[ch] = r;
        }
    }
}

extern "C" void kernel_launch(void* const* d_in, const int* in_sizes, int n_in,
                              void* d_out, int out_size) {
    // Map inputs by element count:
    //   x: 4096*256 = 1048576, pos_l: 4096*3 = 12288, pos_h: 16384*3 = 49152
    const float* x     = nullptr;
    const float* pos_l = nullptr;
    const float* pos_h = nullptr;
    for (int i = 0; i < n_in; ++i) {
        if      (in_sizes[i] == NL * NF) x     = (const float*)d_in[i];
        else if (in_sizes[i] == NL * 3)  pos_l = (const float*)d_in[i];
        else if (in_sizes[i] == NH * 3)  pos_h = (const float*)d_in[i];
    }
    float* out = (float*)d_out;
    knn_interp_kernel<<<GRID, TPB>>>(x, pos_l, pos_h, out);
}

// round 13
// speedup vs baseline: 1.1930x; 1.1930x over previous
#include <cuda_runtime.h>
#include <cstdint>

static constexpr int NL   = 4096;    // coarse points
static constexpr int NH   = 16384;   // fine points
static constexpr int NF   = 256;     // features
static constexpr int PPB  = 112;     // fine points per block (147 blocks -> 147/148 SMs)
static constexpr int SUBS = 8;       // candidate slices
static constexpr int TPB  = PPB * SUBS;   // 896 threads, 28 warps
static constexpr int GRID = (NH + PPB - 1) / PPB;  // 147
static constexpr int NPAIR = NL / 2;       // 2048 staged pairs (whole table, 64 KB)
static constexpr int WPAIR = NPAIR / SUBS; // 256 pairs per sub
static constexpr int SMEM_BYTES = NL * 16; // 64 KB dynamic

// packed f32x2 helpers (sm_103a FFMA2 — PTX-only, ptxas never auto-fuses)
__device__ __forceinline__ uint64_t ffma2(uint64_t a, uint64_t b, uint64_t c) {
    uint64_t d;
    asm("fma.rn.f32x2 %0, %1, %2, %3;" : "=l"(d) : "l"(a), "l"(b), "l"(c));
    return d;
}
__device__ __forceinline__ uint64_t pack2(float lo, float hi) {
    uint64_t r;
    asm("mov.b64 %0, {%1, %2};" : "=l"(r) : "f"(lo), "f"(hi));
    return r;
}
__device__ __forceinline__ void unpack2(float& lo, float& hi, uint64_t v) {
    asm("mov.b64 {%0, %1}, %2;" : "=f"(lo), "=f"(hi) : "l"(v));
}

__global__ __launch_bounds__(TPB, 1)
void knn_interp_kernel(const float* __restrict__ x,
                       const float* __restrict__ pos_l,
                       const float* __restrict__ pos_h,
                       float* __restrict__ out)
{
    // 64 KB dynamic buffer: whole pair-packed candidate table during the scan,
    // then reused (after a barrier) for the per-sub merge arrays (~21.5 KB).
    extern __shared__ __align__(16) char smemBuf[];
    __shared__ int   sIdx[PPB][3];
    __shared__ float sW[PPB][3];

    // QA[j] = (xpair, ypair), QB[j] = (zpair, wpair); x=-2lx etc., w=|l|^2
    ulonglong2* sQA = reinterpret_cast<ulonglong2*>(smemBuf);               // 32 KB
    ulonglong2* sQB = reinterpret_cast<ulonglong2*>(smemBuf + NPAIR*16);    // 32 KB
    float (*sMs)[PPB][3] = reinterpret_cast<float (*)[PPB][3]>(smemBuf);
    int   (*sMi)[PPB][3] = reinterpret_cast<int   (*)[PPB][3]>(smemBuf + SUBS*PPB*3*4);

    const int tid  = threadIdx.x;
    const int sub  = tid / PPB;        // 0..7 : candidate slice
    const int p    = tid - sub * PPB;  // 0..111 : fine point within block
    const int hbase = blockIdx.x * PPB;
    const int npts = min(PPB, NH - hbase);        // tail block: 32 valid points
    const int h    = hbase + min(p, npts - 1);    // clamp: invalid lanes discarded later

    const float hx = pos_h[3*h+0];
    const float hy = pos_h[3*h+1];
    const float hz = pos_h[3*h+2];
    const uint64_t hx2 = pack2(hx, hx);
    const uint64_t hy2 = pack2(hy, hy);
    const uint64_t hz2 = pack2(hz, hz);

    // stage the whole candidate table once (float2-vectorized gmem reads)
    {
        const float2* __restrict__ pl2 = reinterpret_cast<const float2*>(pos_l);
        for (int pj = tid; pj < NPAIR; pj += TPB) {
            const float2 v0 = pl2[3*pj+0];   // ax ay
            const float2 v1 = pl2[3*pj+1];   // az bx
            const float2 v2 = pl2[3*pj+2];   // by bz
            const float ax = v0.x, ay = v0.y, az = v1.x;
            const float bx = v1.y, by = v2.x, bz = v2.y;
            const float wa = fmaf(ax, ax, fmaf(ay, ay, az*az));
            const float wb = fmaf(bx, bx, fmaf(by, by, bz*bz));
            sQA[pj] = make_ulonglong2(pack2(-2.0f*ax, -2.0f*bx),
                                      pack2(-2.0f*ay, -2.0f*by));
            sQB[pj] = make_ulonglong2(pack2(-2.0f*az, -2.0f*bz),
                                      pack2(wa, wb));
        }
    }
    __syncthreads();

    // Partial top-3 by score = |l|^2 - 2 h.l (bit-identical to flat-scan R5/R8/R11)
    float s0 = 3.4e38f, s1 = 3.4e38f, s2 = 3.4e38f;
    int   i0 = 0, i1 = 0, i2 = 0;

    auto insert = [&](float s, int g) {   // same nested form as R5/R8/R11 (proven codegen)
        if (s < s1) {
            s2 = s1; i2 = i1;
            if (s < s0) { s1 = s0; i1 = i0; s0 = s; i0 = g; }
            else        { s1 = s;  i1 = g; }
        } else { s2 = s; i2 = g; }
    };

    {
        const int pb = sub * WPAIR;            // warp-level LDS broadcast/coalesced
        const int gb = 2 * pb;
        #pragma unroll 8
        for (int jp = 0; jp < WPAIR; ++jp) {
            const ulonglong2 qa = sQA[pb + jp];   // (xpair, ypair)
            const ulonglong2 qb = sQB[pb + jp];   // (zpair, wpair)
            uint64_t t = ffma2(qb.x, hz2, qb.y);
            t = ffma2(qa.y, hy2, t);
            t = ffma2(qa.x, hx2, t);
            float sa, sb;
            unpack2(sa, sb, t);
            const int g = gb + 2*jp;
            if (sa < s2) insert(sa, g);       // sequential order preserved:
            if (sb < s2) insert(sb, g + 1);   // a first, then b
        }
    }

    __syncthreads();   // all reads of sQA/sQB done -> safe to alias as merge buffers
    sMs[sub][p][0] = s0; sMs[sub][p][1] = s1; sMs[sub][p][2] = s2;
    sMi[sub][p][0] = i0; sMi[sub][p][1] = i1; sMi[sub][p][2] = i2;
    __syncthreads();

    // Merge 8 partial top-3s -> final top-3; exact-d2 weights.
    // Threads tid<npts have p==tid, so (hx,hy,hz) already hold this point's coords.
    if (tid < npts) {
        float b0 = 3.4e38f, b1 = 3.4e38f, b2 = 3.4e38f;
        int   j0 = 0, j1 = 0, j2 = 0;
        #pragma unroll
        for (int ss = 0; ss < SUBS; ++ss) {
            #pragma unroll
            for (int k = 0; k < 3; ++k) {
                const float s = sMs[ss][tid][k];
                const int   g = sMi[ss][tid][k];
                if (s < b2) {
                    if (s < b1) {
                        b2 = b1; j2 = j1;
                        if (s < b0) { b1 = b0; j1 = j0; b0 = s; j0 = g; }
                        else        { b1 = s;  j1 = g; }
                    } else { b2 = s; j2 = g; }
                }
            }
        }
        // Exact squared distances for the 3 selected (matches reference recompute)
        const int id[3] = {j0, j1, j2};
        float w[3], wsum = 0.0f;
        #pragma unroll
        for (int k = 0; k < 3; ++k) {
            const float lx = pos_l[3*id[k]+0];
            const float ly = pos_l[3*id[k]+1];
            const float lz = pos_l[3*id[k]+2];
            const float dx = hx - lx, dy = hy - ly, dz = hz - lz;
            const float d2 = fmaf(dx, dx, fmaf(dy, dy, dz*dz));
            const float wk = 1.0f / fmaxf(d2, 1e-16f);
            w[k] = wk;
            wsum += wk;
        }
        const float inv = 1.0f / wsum;
        sIdx[tid][0] = id[0]; sIdx[tid][1] = id[1]; sIdx[tid][2] = id[2];
        sW[tid][0] = w[0]*inv; sW[tid][1] = w[1]*inv; sW[tid][2] = w[2]*inv;
    }
    __syncthreads();

    // Phase B: gather + weighted sum. One warp per fine point, float4-coalesced.
    const int warp = tid >> 5, lane = tid & 31;   // 28 warps
    const float4* __restrict__ x4 = reinterpret_cast<const float4*>(x);
    float4* __restrict__ o4 = reinterpret_cast<float4*>(out);
    const int rowq = NF / 4;   // 64 float4 per feature row

    for (int pp = warp; pp < npts; pp += 28) {
        const int hh = hbase + pp;
        const int a = sIdx[pp][0], b = sIdx[pp][1], c = sIdx[pp][2];
        const float w0 = sW[pp][0], w1 = sW[pp][1], w2 = sW[pp][2];
        const float4* __restrict__ ra = x4 + a * rowq;
        const float4* __restrict__ rb = x4 + b * rowq;
        const float4* __restrict__ rc = x4 + c * rowq;
        float4* __restrict__ ro = o4 + hh * rowq;
        #pragma unroll
        for (int ch = lane; ch < rowq; ch += 32) {
            const float4 va = ra[ch];
            const float4 vb = rb[ch];
            const float4 vc = rc[ch];
            float4 r;
            r.x = fmaf(w2, vc.x, fmaf(w1, vb.x, w0 * va.x));
            r.y = fmaf(w2, vc.y, fmaf(w1, vb.y, w0 * va.y));
            r.z = fmaf(w2, vc.z, fmaf(w1, vb.z, w0 * va.z));
            r.w = fmaf(w2, vc.w, fmaf(w1, vb.w, w0 * va.w));
            ro[ch] = r;
        }
    }
}

extern "C" void kernel_launch(void* const* d_in, const int* in_sizes, int n_in,
                              void* d_out, int out_size) {
    // Map inputs by element count:
    //   x: 4096*256 = 1048576, pos_l: 4096*3 = 12288, pos_h: 16384*3 = 49152
    const float* x     = nullptr;
    const float* pos_l = nullptr;
    const float* pos_h = nullptr;
    for (int i = 0; i < n_in; ++i) {
        if      (in_sizes[i] == NL * NF) x     = (const float*)d_in[i];
        else if (in_sizes[i] == NL * 3)  pos_l = (const float*)d_in[i];
        else if (in_sizes[i] == NH * 3)  pos_h = (const float*)d_in[i];
    }
    float* out = (float*)d_out;
    cudaFuncSetAttribute(knn_interp_kernel,
                         cudaFuncAttributeMaxDynamicSharedMemorySize, SMEM_BYTES);
    knn_interp_kernel<<<GRID, TPB, SMEM_BYTES>>>(x, pos_l, pos_h, out);
}